// round 5
// baseline (speedup 1.0000x reference)
#include <cuda_runtime.h>
#include <cuda_bf16.h>
#include <math.h>
#include <stdint.h>

#define BATCH 8
#define NPTS 4096
#define SPTS 1024
#define D1 128
#define D2 256
#define INCH 384
#define OUTCH 256
#define NTOT (BATCH * NPTS)   // 32768
#define BN_EPS 1e-5f
#define WTOT (OUTCH * INCH + 2 * OUTCH * OUTCH)   // 229376

// ---------------- scratch (device globals; no allocs allowed) ----------------
__device__ __align__(256) __nv_bfloat16 g_Xh[(size_t)NTOT * INCH];
__device__ __align__(256) __nv_bfloat16 g_Xl[(size_t)NTOT * INCH];
__device__ __align__(256) __nv_bfloat16 g_A1h[(size_t)NTOT * OUTCH];
__device__ __align__(256) __nv_bfloat16 g_A1l[(size_t)NTOT * OUTCH];
__device__ __align__(256) __nv_bfloat16 g_A2h[(size_t)NTOT * OUTCH];
__device__ __align__(256) __nv_bfloat16 g_A2l[(size_t)NTOT * OUTCH];
__device__ __align__(256) float g_Z[(size_t)NTOT * OUTCH];   // sample-major [32768][256]
__device__ __align__(256) __nv_bfloat16 g_Wh[WTOT];
__device__ __align__(256) __nv_bfloat16 g_Wl[WTOT];
__device__ float g_w3[NTOT * 3];
__device__ int   g_i3[NTOT * 3];
__device__ float g_psum[OUTCH];
__device__ float g_psq[OUTCH];
__device__ float g_scale[OUTCH];
__device__ float g_shift[OUTCH];

// ---------------- helpers ----------------
__device__ __forceinline__ uint32_t smem_to_u32(const void* p) {
    uint32_t a;
    asm("{ .reg .u64 t; cvta.to.shared.u64 t, %1; cvt.u32.u64 %0, t; }" : "=r"(a) : "l"(p));
    return a;
}
#define SMZ(o) ((o) ^ (((o) >> 3) & 0x70))
#define CP16(dst, src) \
    asm volatile("cp.async.cg.shared.global [%0], [%1], 16;" :: "r"(dst), "l"(src) : "memory")
template <int N>
__device__ __forceinline__ void cp_wait() {
    asm volatile("cp.async.wait_group %0;" :: "n"(N) : "memory");
}

__device__ __forceinline__ void ldsm_x4(uint32_t& r0, uint32_t& r1, uint32_t& r2, uint32_t& r3,
                                        uint32_t addr) {
    asm volatile("ldmatrix.sync.aligned.m8n8.x4.shared.b16 {%0,%1,%2,%3}, [%4];"
                 : "=r"(r0), "=r"(r1), "=r"(r2), "=r"(r3) : "r"(addr));
}
__device__ __forceinline__ void mma_bf16(float& c0, float& c1, float& c2, float& c3,
                                         uint32_t a0, uint32_t a1, uint32_t a2, uint32_t a3,
                                         uint32_t b0, uint32_t b1) {
    asm volatile("mma.sync.aligned.m16n8k16.row.col.f32.bf16.bf16.f32 "
                 "{%0,%1,%2,%3}, {%4,%5,%6,%7}, {%8,%9}, {%0,%1,%2,%3};"
                 : "+f"(c0), "+f"(c1), "+f"(c2), "+f"(c3)
                 : "r"(a0), "r"(a1), "r"(a2), "r"(a3), "r"(b0), "r"(b1));
}

__device__ __forceinline__ float gelu_exact(float x) {
    return 0.5f * x * (1.0f + erff(x * 0.70710678118654752f));
}
__device__ __forceinline__ uint32_t pack_bf16(float a, float b) {
    __nv_bfloat162 t = __floats2bfloat162_rn(a, b);
    return *reinterpret_cast<uint32_t*>(&t);
}

// ---------------- kernel 1: per-sample top-3 neighbors + weights ----------------
__global__ __launch_bounds__(256) void topk_kernel(
    const float* __restrict__ xyz1, const float* __restrict__ xyz2)
{
    __shared__ float4 q[SPTS];
    const int b = blockIdx.y;
    const int n = blockIdx.x * blockDim.x + threadIdx.x;

    for (int s = threadIdx.x; s < SPTS; s += blockDim.x) {
        const float* p = xyz2 + ((size_t)b * SPTS + s) * 3;
        float x = p[0], y = p[1], z = p[2];
        q[s] = make_float4(x, y, z, x * x + y * y + z * z);
    }
    __syncthreads();

    const float* p = xyz1 + ((size_t)b * NPTS + n) * 3;
    float px = p[0], py = p[1], pz = p[2];
    float rn = px * px + py * py + pz * pz;

    float d0 = 3.4e38f, d1 = 3.4e38f, d2 = 3.4e38f;
    int i0 = 0, i1 = 0, i2 = 0;
    #pragma unroll 4
    for (int s = 0; s < SPTS; s++) {
        float4 qq = q[s];
        float d = rn - 2.0f * (px * qq.x + py * qq.y + pz * qq.z) + qq.w;
        if (d < d2) {
            if (d < d1) {
                if (d < d0) { d2 = d1; i2 = i1; d1 = d0; i1 = i0; d0 = d; i0 = s; }
                else        { d2 = d1; i2 = i1; d1 = d;  i1 = s; }
            } else          { d2 = d;  i2 = s; }
        }
    }
    float r0 = 1.0f / (d0 + 1e-8f);
    float r1 = 1.0f / (d1 + 1e-8f);
    float r2 = 1.0f / (d2 + 1e-8f);
    float rs = 1.0f / (r0 + r1 + r2);
    const int sample = b * NPTS + n;
    g_w3[sample * 3 + 0] = r0 * rs;
    g_w3[sample * 3 + 1] = r1 * rs;
    g_w3[sample * 3 + 2] = r2 * rs;
    g_i3[sample * 3 + 0] = i0;
    g_i3[sample * 3 + 1] = i1;
    g_i3[sample * 3 + 2] = i2;
}

// ---------------- kernel 2: build fused input in bf16 hi/lo, sample-major ----------------
__global__ __launch_bounds__(384) void build_input(
    const float* __restrict__ points1, const float* __restrict__ points2)
{
    __shared__ float w[3];
    __shared__ int id[3];
    const int n = blockIdx.x;
    if (threadIdx.x < 3) {
        w[threadIdx.x]  = g_w3[n * 3 + threadIdx.x];
        id[threadIdx.x] = g_i3[n * 3 + threadIdx.x];
    }
    __syncthreads();
    const int c = threadIdx.x;
    float v;
    if (c < D1) {
        v = __ldg(points1 + (size_t)n * D1 + c);
    } else {
        const int b = n >> 12;
        const int cc = c - D1;
        const float* base = points2 + (size_t)b * SPTS * D2 + cc;
        v = w[0] * __ldg(base + (size_t)id[0] * D2)
          + w[1] * __ldg(base + (size_t)id[1] * D2)
          + w[2] * __ldg(base + (size_t)id[2] * D2);
    }
    __nv_bfloat16 h = __float2bfloat16(v);
    __nv_bfloat16 l = __float2bfloat16(v - __bfloat162float(h));
    g_Xh[(size_t)n * INCH + c] = h;
    g_Xl[(size_t)n * INCH + c] = l;
}

// ---------------- kernel 3: weights fp32 -> bf16 hi/lo + zero stat accumulators ----------------
__global__ __launch_bounds__(256) void wsplit_all(
    const float* __restrict__ Wf, const float* __restrict__ W1, const float* __restrict__ W2)
{
    int i = blockIdx.x * 256 + threadIdx.x;
    if (i < OUTCH) { g_psum[i] = 0.0f; g_psq[i] = 0.0f; }
    if (i >= WTOT) return;
    float w;
    if (i < OUTCH * INCH)                      w = Wf[i];
    else if (i < OUTCH * INCH + OUTCH * OUTCH) w = W1[i - OUTCH * INCH];
    else                                       w = W2[i - OUTCH * INCH - OUTCH * OUTCH];
    __nv_bfloat16 h = __float2bfloat16(w);
    g_Wh[i] = h;
    g_Wl[i] = __float2bfloat16(w - __bfloat162float(h));
}

// ---------------- GEMM via mma.sync: Z[sample][ch] = X @ W^T + bias, fused stats ----------------
// CTA 128x128, BK=64, 3-stage cp.async pipeline, single __syncthreads per chunk,
// 3 compensation segments (Xh*Wh + Xl*Wh + Xh*Wl), fp32 accum.
#define STAGE_SZ 32768
#define NSTAGE 3
#define GEMM_SMEM (NSTAGE * STAGE_SZ + 512)

__device__ __forceinline__ void load_tile128(uint32_t dst, const __nv_bfloat16* src,
                                             int ldK, int row0, int k0, int tid) {
    #pragma unroll
    for (int j = 0; j < 4; j++) {
        int g = tid + j * 256;
        int r = g >> 3;
        int c16 = (g & 7) * 16;
        const char* s = (const char*)(src + (size_t)(row0 + r) * ldK + k0) + c16;
        CP16(dst + SMZ(r * 128 + c16), s);
    }
}

template <int K>
__global__ __launch_bounds__(256, 2) void gemm_mma(
    const __nv_bfloat16* __restrict__ Xh, const __nv_bfloat16* __restrict__ Xl,
    const float* __restrict__ bias, int woff)
{
    constexpr int KC = K / 64;       // chunks per segment
    constexpr int NC = 3 * KC;       // total chunks (3 compensation segments)
    extern __shared__ char smem[];
    const uint32_t sb = smem_to_u32(smem);
    const int tid = threadIdx.x;
    const int wid = tid >> 5;
    const int lane = tid & 31;
    const int sample0 = blockIdx.x * 128;
    const int n0 = blockIdx.y * 128;

    const int mWarp = (wid & 1) * 64;
    const int nWarp = (wid >> 1) * 32;

    if (tid < 128) ((float*)(smem + NSTAGE * STAGE_SZ))[tid] = bias[n0 + tid];

    const __nv_bfloat16* Wh = g_Wh + woff;
    const __nv_bfloat16* Wl = g_Wl + woff;
    const __nv_bfloat16* Aseg[3] = {Xh, Xl, Xh};
    const __nv_bfloat16* Bseg[3] = {Wh, Wh, Wl};

    // prologue: load chunks 0,1 into stages 0,1
    #pragma unroll
    for (int i = 0; i < 2; i++) {
        const int seg = i / KC, kk = (i % KC) * 64;
        const uint32_t st = sb + i * STAGE_SZ;
        load_tile128(st,         Aseg[seg], K, sample0, kk, tid);
        load_tile128(st + 16384, Bseg[seg], K, n0,      kk, tid);
        asm volatile("cp.async.commit_group;" ::: "memory");
    }

    float acc[4][4][4];
    #pragma unroll
    for (int a = 0; a < 4; a++)
        #pragma unroll
        for (int b = 0; b < 4; b++)
            #pragma unroll
            for (int c = 0; c < 4; c++) acc[a][b][c] = 0.0f;

    const int aRow = mWarp + (lane & 15);
    const int aColHalf = (lane >> 4) * 16;             // bytes
    const int bRow = nWarp + ((lane >> 4) << 3) + (lane & 7);
    const int bColHalf = ((lane >> 3) & 1) * 16;       // bytes

    cp_wait<1>();              // chunk 0 arrived
    __syncthreads();

    int stage = 0;
    for (int i = 0; i < NC; i++) {
        // issue next load first (into the stage freed by last iteration's barrier)
        if (i + 2 < NC) {
            const int j = i + 2;
            const int seg = j / KC, kk = (j % KC) * 64;
            const uint32_t st = sb + ((j >= NSTAGE) ? (j % NSTAGE) : j) * STAGE_SZ;
            load_tile128(st,         Aseg[seg], K, sample0, kk, tid);
            load_tile128(st + 16384, Bseg[seg], K, n0,      kk, tid);
            asm volatile("cp.async.commit_group;" ::: "memory");
        }

        const uint32_t sA = sb + stage * STAGE_SZ;
        const uint32_t sB = sA + 16384;

        #pragma unroll
        for (int k16 = 0; k16 < 4; k16++) {
            uint32_t af[4][4];
            #pragma unroll
            for (int mb = 0; mb < 4; mb++) {
                uint32_t addr = sA + SMZ((aRow + mb * 16) * 128 + k16 * 32 + aColHalf);
                ldsm_x4(af[mb][0], af[mb][1], af[mb][2], af[mb][3], addr);
            }
            uint32_t bf[2][4];
            #pragma unroll
            for (int p = 0; p < 2; p++) {
                uint32_t addr = sB + SMZ((bRow + p * 16) * 128 + k16 * 32 + bColHalf);
                ldsm_x4(bf[p][0], bf[p][1], bf[p][2], bf[p][3], addr);
            }
            #pragma unroll
            for (int mb = 0; mb < 4; mb++)
                #pragma unroll
                for (int nb = 0; nb < 4; nb++) {
                    uint32_t b0 = bf[nb >> 1][(nb & 1) * 2];
                    uint32_t b1 = bf[nb >> 1][(nb & 1) * 2 + 1];
                    mma_bf16(acc[mb][nb][0], acc[mb][nb][1], acc[mb][nb][2], acc[mb][nb][3],
                             af[mb][0], af[mb][1], af[mb][2], af[mb][3], b0, b1);
                }
        }

        // retire: ensure chunk i+1 data present for next iteration, then barrier
        if (i + 1 < NC) {
            if (i + 2 < NC) cp_wait<1>();
            else            cp_wait<0>();
            __syncthreads();
        }
        stage = (stage + 1 == NSTAGE) ? 0 : stage + 1;
    }

    // epilogue: add bias, write fp32 Z (sample-major), fused per-channel stats
    const float* sbias = (const float*)(smem + NSTAGE * STAGE_SZ);
    const int rr = lane >> 2;            // 0..7
    const int cc = (lane & 3) * 2;       // 0..6
    #pragma unroll
    for (int nb = 0; nb < 4; nb++) {
        const int col = nWarp + nb * 8 + cc;       // within 128-col tile
        const float b0 = sbias[col], b1 = sbias[col + 1];
        float cs0 = 0.0f, cs1 = 0.0f, cq0 = 0.0f, cq1 = 0.0f;
        #pragma unroll
        for (int mb = 0; mb < 4; mb++) {
            const int row0 = sample0 + mWarp + mb * 16 + rr;
            float v00 = acc[mb][nb][0] + b0;
            float v01 = acc[mb][nb][1] + b1;
            float v10 = acc[mb][nb][2] + b0;
            float v11 = acc[mb][nb][3] + b1;
            *(float2*)(g_Z + (size_t)row0 * OUTCH + n0 + col)       = make_float2(v00, v01);
            *(float2*)(g_Z + (size_t)(row0 + 8) * OUTCH + n0 + col) = make_float2(v10, v11);
            cs0 += v00 + v10;
            cs1 += v01 + v11;
            cq0 += v00 * v00 + v10 * v10;
            cq1 += v01 * v01 + v11 * v11;
        }
        // reduce over the 8 lanes sharing this column pair (lane bits 2..4)
        #pragma unroll
        for (int off = 4; off <= 16; off <<= 1) {
            cs0 += __shfl_xor_sync(0xFFFFFFFF, cs0, off);
            cs1 += __shfl_xor_sync(0xFFFFFFFF, cs1, off);
            cq0 += __shfl_xor_sync(0xFFFFFFFF, cq0, off);
            cq1 += __shfl_xor_sync(0xFFFFFFFF, cq1, off);
        }
        if (lane < 4) {
            atomicAdd(&g_psum[n0 + col],     cs0);
            atomicAdd(&g_psum[n0 + col + 1], cs1);
            atomicAdd(&g_psq[n0 + col],      cq0);
            atomicAdd(&g_psq[n0 + col + 1],  cq1);
        }
    }
}

// ---------------- stats2: finalize scale/shift, re-zero accumulators ----------------
__global__ __launch_bounds__(256) void stats2(
    const float* __restrict__ gamma, const float* __restrict__ beta)
{
    const int c = threadIdx.x;
    float s = g_psum[c];
    float q = g_psq[c];
    float m = s * (1.0f / NTOT);
    float var = q * (1.0f / NTOT) - m * m;
    float r = rsqrtf(var + BN_EPS);
    float sc = r * gamma[c];
    g_scale[c] = sc;
    g_shift[c] = beta[c] - m * sc;
    g_psum[c] = 0.0f;      // ready for next layer / next replay
    g_psq[c] = 0.0f;
}

// ---------------- BN + GELU -> bf16 hi/lo activation ----------------
__global__ __launch_bounds__(256) void bn_act(
    __nv_bfloat16* __restrict__ Ah, __nv_bfloat16* __restrict__ Al)
{
    const int idx4 = blockIdx.x * 256 + threadIdx.x;
    const int c4 = (idx4 & 63) * 4;
    float4 z = ((const float4*)g_Z)[idx4];
    float4 sc = *(const float4*)(g_scale + c4);
    float4 sh = *(const float4*)(g_shift + c4);
    float a0 = gelu_exact(fmaf(z.x, sc.x, sh.x));
    float a1 = gelu_exact(fmaf(z.y, sc.y, sh.y));
    float a2 = gelu_exact(fmaf(z.z, sc.z, sh.z));
    float a3 = gelu_exact(fmaf(z.w, sc.w, sh.w));
    uint2 hv, lv;
    hv.x = pack_bf16(a0, a1);
    hv.y = pack_bf16(a2, a3);
    float h0 = __bfloat162float(__float2bfloat16(a0));
    float h1 = __bfloat162float(__float2bfloat16(a1));
    float h2 = __bfloat162float(__float2bfloat16(a2));
    float h3 = __bfloat162float(__float2bfloat16(a3));
    lv.x = pack_bf16(a0 - h0, a1 - h1);
    lv.y = pack_bf16(a2 - h2, a3 - h3);
    ((uint2*)Ah)[idx4] = hv;
    ((uint2*)Al)[idx4] = lv;
}

// ---------------- final: BN + residual + GELU -> out (sample-major already) ----------------
__global__ __launch_bounds__(256) void final_k(float* __restrict__ out) {
    const int idx4 = blockIdx.x * 256 + threadIdx.x;
    const int c4 = (idx4 & 63) * 4;
    float4 z = ((const float4*)g_Z)[idx4];
    float4 sc = *(const float4*)(g_scale + c4);
    float4 sh = *(const float4*)(g_shift + c4);
    uint2 hv = ((const uint2*)g_A1h)[idx4];
    uint2 lv = ((const uint2*)g_A1l)[idx4];
    __nv_bfloat162 h01 = *(__nv_bfloat162*)&hv.x;
    __nv_bfloat162 h23 = *(__nv_bfloat162*)&hv.y;
    __nv_bfloat162 l01 = *(__nv_bfloat162*)&lv.x;
    __nv_bfloat162 l23 = *(__nv_bfloat162*)&lv.y;
    float r0 = __bfloat162float(h01.x) + __bfloat162float(l01.x);
    float r1 = __bfloat162float(h01.y) + __bfloat162float(l01.y);
    float r2 = __bfloat162float(h23.x) + __bfloat162float(l23.x);
    float r3 = __bfloat162float(h23.y) + __bfloat162float(l23.y);
    float4 o;
    o.x = gelu_exact(fmaf(z.x, sc.x, sh.x) + r0);
    o.y = gelu_exact(fmaf(z.y, sc.y, sh.y) + r1);
    o.z = gelu_exact(fmaf(z.z, sc.z, sh.z) + r2);
    o.w = gelu_exact(fmaf(z.w, sc.w, sh.w) + r3);
    ((float4*)out)[idx4] = o;
}

// ---------------- launch ----------------
extern "C" void kernel_launch(void* const* d_in, const int* in_sizes, int n_in,
                              void* d_out, int out_size) {
    const float* xyz1    = (const float*)d_in[0];
    const float* xyz2    = (const float*)d_in[1];
    const float* points1 = (const float*)d_in[2];
    const float* points2 = (const float*)d_in[3];
    const float* W_fuse  = (const float*)d_in[4];
    const float* b_fuse  = (const float*)d_in[5];
    const float* g_fuse  = (const float*)d_in[6];
    const float* bt_fuse = (const float*)d_in[7];
    const float* W1      = (const float*)d_in[8];
    const float* b1      = (const float*)d_in[9];
    const float* g1      = (const float*)d_in[10];
    const float* bt1     = (const float*)d_in[11];
    const float* W2      = (const float*)d_in[12];
    const float* b2      = (const float*)d_in[13];
    const float* g2      = (const float*)d_in[14];
    const float* bt2     = (const float*)d_in[15];
    float* out = (float*)d_out;

    __nv_bfloat16 *pXh, *pXl, *pA1h, *pA1l, *pA2h, *pA2l;
    cudaGetSymbolAddress((void**)&pXh,  g_Xh);
    cudaGetSymbolAddress((void**)&pXl,  g_Xl);
    cudaGetSymbolAddress((void**)&pA1h, g_A1h);
    cudaGetSymbolAddress((void**)&pA1l, g_A1l);
    cudaGetSymbolAddress((void**)&pA2h, g_A2h);
    cudaGetSymbolAddress((void**)&pA2l, g_A2l);

    cudaFuncSetAttribute(gemm_mma<INCH>,  cudaFuncAttributeMaxDynamicSharedMemorySize, GEMM_SMEM);
    cudaFuncSetAttribute(gemm_mma<OUTCH>, cudaFuncAttributeMaxDynamicSharedMemorySize, GEMM_SMEM);

    const dim3 gemm_grid(NTOT / 128, OUTCH / 128);
    const int bn_blocks = (OUTCH * NTOT / 4) / 256;   // 8192

    wsplit_all<<<(WTOT + 255) / 256, 256>>>(W_fuse, W1, W2);
    topk_kernel<<<dim3(NPTS / 256, BATCH), 256>>>(xyz1, xyz2);
    build_input<<<NTOT, 384>>>(points1, points2);

    const int woff_f = 0;
    const int woff_1 = OUTCH * INCH;
    const int woff_2 = OUTCH * INCH + OUTCH * OUTCH;

    // layer fuse
    gemm_mma<INCH><<<gemm_grid, 256, GEMM_SMEM>>>(pXh, pXl, b_fuse, woff_f);
    stats2<<<1, 256>>>(g_fuse, bt_fuse);
    bn_act<<<bn_blocks, 256>>>(pA1h, pA1l);

    // layer 1
    gemm_mma<OUTCH><<<gemm_grid, 256, GEMM_SMEM>>>(pA1h, pA1l, b1, woff_1);
    stats2<<<1, 256>>>(g1, bt1);
    bn_act<<<bn_blocks, 256>>>(pA2h, pA2l);

    // layer 2 + residual + output
    gemm_mma<OUTCH><<<gemm_grid, 256, GEMM_SMEM>>>(pA2h, pA2l, b2, woff_2);
    stats2<<<1, 256>>>(g2, bt2);
    final_k<<<bn_blocks, 256>>>(out);
}